// round 9
// baseline (speedup 1.0000x reference)
#include <cuda_runtime.h>
#include <cuda_fp16.h>
#include <math.h>
#include <stdint.h>

#define NT 16384
#define NE 16384
#define BETA 0.25f

#define RS2 136                     // halves per padded row (128 data + 8 pad)
#define RB2 272                     // bytes per row (17*16 -> conflict-free ldmatrix)
#define TILE2_BYTES (128 * RB2)     // 34816
#define CHUNK2 (TILE2_BYTES / 16)   // 2176

#define NCH 8                       // N chunks (partial argmin, merged later)
#define SPC 16                      // subtiles per chunk (8*16 = 128)

// ---------------- static device scratch ----------------
__device__ __half g_zf[16384 * RS2];  // A = [h_z | l_z], padded rows
__device__ __half g_ef[16384 * RS2];  // B = [h_E | l_E], E = 4096*e
__device__ float g_enorm[NE];
__device__ float g_znorm[NT];
__device__ float g_pval[NCH * NT];
__device__ int   g_pidx[NCH * NT];
__device__ int   g_idx[NT];
__device__ int   g_counts[NE];
__device__ float g_loss;
__device__ float g_ent;
__device__ int   g_cu;
__device__ int   g_tick;

// ---------------- helpers ----------------
__device__ __forceinline__ uint32_t smem_u32(const void* p) {
    uint32_t a;
    asm("{ .reg .u64 t; cvta.to.shared.u64 t, %1; cvt.u32.u64 %0, t; }" : "=r"(a) : "l"(p));
    return a;
}
__device__ __forceinline__ void split2h(float v, __half& h, __half& l) {
    __half hh = __float2half_rn(v);
    float r = __fsub_rn(v, __half2float(hh));   // exact
    h = hh; l = __float2half_rn(r);
}

#define CP_ASYNC16(dst_u32, src_ptr) \
    asm volatile("cp.async.cg.shared.global [%0], [%1], 16;\n" :: "r"(dst_u32), "l"(src_ptr))
#define CP_COMMIT()  asm volatile("cp.async.commit_group;\n" ::: "memory")
#define CP_WAIT0()   asm volatile("cp.async.wait_group 0;\n" ::: "memory")

#define LDSM_X4(r, addr) \
    asm volatile("ldmatrix.sync.aligned.m8n8.x4.shared.b16 {%0,%1,%2,%3}, [%4];" \
        : "=r"((r)[0]), "=r"((r)[1]), "=r"((r)[2]), "=r"((r)[3]) : "r"(addr))
#define LDSM_X2(r, addr) \
    asm volatile("ldmatrix.sync.aligned.m8n8.x2.shared.b16 {%0,%1}, [%2];" \
        : "=r"((r)[0]), "=r"((r)[1]) : "r"(addr))

__device__ __forceinline__ void mma16816(float* c, const uint32_t* a, const uint32_t* b) {
    asm volatile(
        "mma.sync.aligned.m16n8k16.row.col.f32.f16.f16.f32 "
        "{%0,%1,%2,%3}, {%4,%5,%6,%7}, {%8,%9}, {%0,%1,%2,%3};"
        : "+f"(c[0]), "+f"(c[1]), "+f"(c[2]), "+f"(c[3])
        : "r"(a[0]), "r"(a[1]), "r"(a[2]), "r"(a[3]), "r"(b[0]), "r"(b[1]));
}

// ---------------- prep (fused): split z and E=4096*e; norms; zero state ----------------
__global__ void k_split(const float* __restrict__ z, const float* __restrict__ emb) {
    extern __shared__ __half st[];          // 128 * RS2 halves = 34816 B
    int blk = blockIdx.x;                   // 0..127 z tiles, 128..255 e subtiles
    int tid = threadIdx.x;                  // 256
    if (blk < 128) {
        int tile = blk;
        int b = tile >> 3, hw0 = (tile & 7) << 7;
        for (int idx = tid; idx < 8192; idx += 256) {
            int k = idx >> 7, tl = idx & 127;
            float v = z[((size_t)(b * 64 + k) << 10) + hw0 + tl];
            __half h, l; split2h(v, h, l);
            st[tl * RS2 + k]      = h;
            st[tl * RS2 + 64 + k] = l;
        }
        __syncthreads();
        float4* dst = (float4*)(g_zf + (size_t)tile * 128 * RS2);
        const float4* src = (const float4*)st;
        for (int i = tid; i < CHUNK2; i += 256) dst[i] = src[i];
        if (tid < 128) {
            float s = 0.f;
            for (int k = 0; k < 64; k++) {
                float v = z[((size_t)(b * 64 + k) << 10) + hw0 + tid];
                s += v * v;
            }
            g_znorm[(tile << 7) + tid] = s;
        }
        if (tile == 0 && tid == 0) { g_loss = 0.f; g_ent = 0.f; g_cu = 0; g_tick = 0; }
    } else {
        int sub = blk - 128;
        int n0 = sub << 7;
        for (int idx = tid; idx < 8192; idx += 256) {
            int nl = idx >> 6, k = idx & 63;
            float v = emb[(size_t)(n0 + nl) * 64 + k] * 4096.0f;   // exact scale
            __half h, l; split2h(v, h, l);
            st[nl * RS2 + k]      = h;
            st[nl * RS2 + 64 + k] = l;
        }
        __syncthreads();
        float4* dst = (float4*)(g_ef + (size_t)sub * 128 * RS2);
        const float4* src = (const float4*)st;
        for (int i = tid; i < CHUNK2; i += 256) dst[i] = src[i];
        if (tid < 128) {
            float s = 0.f;
            for (int k = 0; k < 64; k++) {
                float v = emb[(size_t)(n0 + tid) * 64 + k];
                s += v * v;
            }
            g_enorm[n0 + tid] = s;
            g_counts[n0 + tid] = 0;
        }
    }
}

// ---------------- building blocks ----------------
__device__ __forceinline__ void load_en(int j, int nbw, int lane, float en[8]) {
#pragma unroll
    for (int ni = 0; ni < 4; ni++) {
        int c0 = nbw + ni * 8 + (lane & 3) * 2;
        en[ni * 2]     = __ldg(&g_enorm[(j << 7) + c0]);
        en[ni * 2 + 1] = __ldg(&g_enorm[(j << 7) + c0 + 1]);
    }
}

// full-subtile mma: A frags loaded ONCE per ks for all 4 ni (R6 structure)
__device__ __forceinline__ void mma_phase(uint32_t a_base, uint32_t b_base,
                                          float acc[4][4][4]) {
#pragma unroll
    for (int mi = 0; mi < 4; mi++)
#pragma unroll
        for (int ni = 0; ni < 4; ni++)
#pragma unroll
            for (int q = 0; q < 4; q++) acc[mi][ni][q] = 0.f;
#pragma unroll
    for (int ks = 0; ks < 4; ks++) {
        uint32_t ah[4][4], al[4][4], bh[4][2], bl[4][2];
#pragma unroll
        for (int mi = 0; mi < 4; mi++) {
            LDSM_X4(ah[mi], a_base + mi * 16 * RB2 + ks * 32);
            LDSM_X4(al[mi], a_base + mi * 16 * RB2 + 128 + ks * 32);
        }
#pragma unroll
        for (int ni = 0; ni < 4; ni++) {
            LDSM_X2(bh[ni], b_base + ni * 8 * RB2 + ks * 32);
            LDSM_X2(bl[ni], b_base + ni * 8 * RB2 + 128 + ks * 32);
        }
#pragma unroll
        for (int mi = 0; mi < 4; mi++)
#pragma unroll
            for (int ni = 0; ni < 4; ni++)
                mma16816(acc[mi][ni], ah[mi], bh[ni]);
#pragma unroll
        for (int mi = 0; mi < 4; mi++)
#pragma unroll
            for (int ni = 0; ni < 4; ni++)
                mma16816(acc[mi][ni], al[mi], bh[ni]);
#pragma unroll
        for (int mi = 0; mi < 4; mi++)
#pragma unroll
            for (int ni = 0; ni < 4; ni++)
                mma16816(acc[mi][ni], ah[mi], bl[ni]);
    }
}

// epilogue: d = fl(fl(zn+en) - acc*2^-11). FMNMX min-tree per row, rare index
// resolve (descending overwrite scan => lowest n among exact-equal values).
__device__ __forceinline__ void epi_tile(const float acc[4][4][4], const float en[8],
                                         const float zn[8], int j, int nbw, int lane,
                                         float bv[8], int bi[8]) {
#pragma unroll
    for (int mi = 0; mi < 4; mi++) {
#pragma unroll
        for (int rh = 0; rh < 2; rh++) {
            int r = mi * 2 + rh;
            float d[4][2];
#pragma unroll
            for (int ni = 0; ni < 4; ni++) {
#pragma unroll
                for (int col = 0; col < 2; col++) {
                    float c = __fadd_rn(zn[r], en[ni * 2 + col]);
                    d[ni][col] = fmaf(acc[mi][ni][rh * 2 + col], -0x1p-11f, c);
                }
            }
            float m = fminf(fminf(fminf(d[0][0], d[0][1]), fminf(d[1][0], d[1][1])),
                            fminf(fminf(d[2][0], d[2][1]), fminf(d[3][0], d[3][1])));
            if (m < bv[r]) {
                bv[r] = m;
                int nb = (j << 7) + nbw + (lane & 3) * 2;
                int sel = nb + 3 * 8 + 1;
#pragma unroll
                for (int ni = 3; ni >= 0; ni--)
#pragma unroll
                    for (int col = 1; col >= 0; col--)
                        if (d[ni][col] == m) sel = nb + ni * 8 + col;
                bi[r] = sel;
            }
        }
    }
}

// ---------------- main: fp16 mma.sync distance GEMM + fused argmin (N-chunked) -------
// smem: A [0,34816) | B0 [34816,69632) | B1 [69632,104448)
#define SM_TOT (3 * TILE2_BYTES)

__global__ void __launch_bounds__(256, 1) k_mma(float* __restrict__ out) {
    extern __shared__ __align__(16) unsigned char sm[];
    uint32_t sb = smem_u32(sm);
    const uint32_t SA = sb, SB0 = sb + TILE2_BYTES, SB1 = sb + 2 * TILE2_BYTES;

    int tid = threadIdx.x, lane = tid & 31, wid = tid >> 5;
    int mw = wid & 1, nw = wid >> 1;        // 2 x 4 warp grid
    int mbase = mw * 64, nbw = nw * 32;     // warp tile 64 x 32

    int tile  = blockIdx.x >> 3;            // 0..127 token tile
    int chunk = blockIdx.x & 7;             // 0..7 N chunk
    int j0 = chunk * SPC;

    // prolog: A tile + B subtile j0
    {
        const char* gz = (const char*)(g_zf + (size_t)tile * 128 * RS2);
        for (int i = tid; i < CHUNK2; i += 256) CP_ASYNC16(SA + i * 16, gz + i * 16);
        const char* ge = (const char*)(g_ef + (size_t)j0 * 128 * RS2);
        for (int i = tid; i < CHUNK2; i += 256) CP_ASYNC16(SB0 + i * 16, ge + i * 16);
        CP_COMMIT(); CP_WAIT0();
    }
    __syncthreads();

    // per-thread rows: r = mbase + mi*16 + rh*8 + (lane>>2)
    float zn[8];
#pragma unroll
    for (int mi = 0; mi < 4; mi++)
#pragma unroll
        for (int rh = 0; rh < 2; rh++)
            zn[mi * 2 + rh] = g_znorm[(tile << 7) + mbase + mi * 16 + rh * 8 + (lane >> 2)];

    float bv[8]; int bi[8];
#pragma unroll
    for (int r = 0; r < 8; r++) { bv[r] = 3.0e38f; bi[r] = 0; }

    // ldmatrix base addresses (conflict-free with 272B row stride)
    uint32_t a_base = SA + (uint32_t)(mbase + (lane & 15)) * RB2 + ((lane >> 4) & 1) * 16;
    uint32_t b_roff = (uint32_t)(nbw + (lane & 7)) * RB2 + ((lane >> 3) & 1) * 16;

    float acc[4][4][4];

    for (int j = j0; j < j0 + SPC; j++) {
        uint32_t Bcur  = (j & 1) ? SB1 : SB0;   // j0 even -> first iter uses SB0
        uint32_t Bnext = (j & 1) ? SB0 : SB1;

        if (j < j0 + SPC - 1) {   // prefetch next B, overlapped with this subtile's mma
            const char* src = (const char*)(g_ef + (size_t)(j + 1) * 128 * RS2);
            for (int i = tid; i < CHUNK2; i += 256) CP_ASYNC16(Bnext + i * 16, src + i * 16);
            CP_COMMIT();
        }

        float en[8];
        load_en(j, nbw, lane, en);

        mma_phase(a_base, Bcur + b_roff, acc);
        epi_tile(acc, en, zn, j, nbw, lane, bv, bi);

        CP_WAIT0();
        __syncthreads();
    }

    // quad reduce (cols within warp): lanes differing in (lane&3)
#pragma unroll
    for (int r = 0; r < 8; r++) {
#pragma unroll
        for (int off = 1; off <= 2; off <<= 1) {
            float ov = __shfl_xor_sync(0xffffffffu, bv[r], off);
            int   oi = __shfl_xor_sync(0xffffffffu, bi[r], off);
            if (ov < bv[r] || (ov == bv[r] && oi < bi[r])) { bv[r] = ov; bi[r] = oi; }
        }
    }
    __syncthreads();
    float* rv = (float*)(sm + TILE2_BYTES);          // reuse B0: 128 rows x 4 nwarps
    int*   ri = (int*)(sm + TILE2_BYTES + 2048);
    if ((lane & 3) == 0) {
#pragma unroll
        for (int r = 0; r < 8; r++) {
            int row = mbase + (r >> 1) * 16 + (r & 1) * 8 + (lane >> 2);
            rv[row * 4 + nw] = bv[r];
            ri[row * 4 + nw] = bi[r];
        }
    }
    __syncthreads();
    if (tid < 128) {
        float v = rv[tid * 4]; int ii = ri[tid * 4];
#pragma unroll
        for (int x = 1; x < 4; x++) {
            float ov = rv[tid * 4 + x]; int oi = ri[tid * 4 + x];
            if (ov < v || (ov == v && oi < ii)) { v = ov; ii = oi; }
        }
        int t = (tile << 7) + tid;
        g_pval[chunk * NT + t] = v;
        g_pidx[chunk * NT + t] = ii;
    }
}

// ---------------- merge chunks -> final idx, histogram, idx-as-float out ----------------
__global__ void k_merge(float* __restrict__ out) {
    int t = blockIdx.x * 1024 + threadIdx.x;   // grid 16 x 1024
    float bv = g_pval[t]; int bi = g_pidx[t];
#pragma unroll
    for (int c = 1; c < NCH; c++) {
        float v = g_pval[c * NT + t]; int ii = g_pidx[c * NT + t];
        if (v < bv || (v == bv && ii < bi)) { bv = v; bi = ii; }
    }
    g_idx[t] = bi;
    out[1048579 + t] = (float)bi;
    atomicAdd(&g_counts[bi], 1);
}

// ---------------- z_q gather + loss accumulation ----------------
__global__ void k_zq(const float* __restrict__ z, const float* __restrict__ emb,
                     float* __restrict__ out) {
    int p = blockIdx.x;            // 1024 planes = (b,c)
    int b = p >> 6, c = p & 63;
    int tid = threadIdx.x;         // 256
    float ls = 0.f;
    for (int hw = tid; hw < 1024; hw += 256) {
        int t = (b << 10) + hw;
        int id = g_idx[t];
        float v  = emb[(size_t)id * 64 + c];
        float zv = z[(size_t)p * 1024 + hw];
        out[(size_t)p * 1024 + hw] = v;
        float df = v - zv;
        ls += df * df;
    }
    __shared__ float red[8];
    for (int o = 16; o > 0; o >>= 1) ls += __shfl_down_sync(0xffffffff, ls, o);
    if ((tid & 31) == 0) red[tid >> 5] = ls;
    __syncthreads();
    if (tid == 0) {
        float s = 0.f;
        for (int w = 0; w < 8; w++) s += red[w];
        atomicAdd(&g_loss, s);
    }
}

// ---------------- entropy (parallel) + final scalar writes (ticket) ----------------
__global__ void k_ent(float* __restrict__ out) {
    int tid = threadIdx.x;                      // 1024, grid 16
    int n = blockIdx.x * 1024 + tid;
    int c = g_counts[n];
    float avg = (float)c * (1.0f / 16384.0f);
    float term = avg * logf(avg + 1e-10f);
    int cu = (c > 0) ? 1 : 0;
    for (int o = 16; o > 0; o >>= 1) {
        term += __shfl_down_sync(0xffffffffu, term, o);
        cu   += __shfl_down_sync(0xffffffffu, cu, o);
    }
    __shared__ float se[32]; __shared__ int sc[32];
    if ((tid & 31) == 0) { se[tid >> 5] = term; sc[tid >> 5] = cu; }
    __syncthreads();
    if (tid == 0) {
        float s = 0.f; int k = 0;
        for (int w = 0; w < 32; w++) { s += se[w]; k += sc[w]; }
        atomicAdd(&g_ent, s);
        atomicAdd(&g_cu, k);
        __threadfence();
        int tk = atomicAdd(&g_tick, 1);
        if (tk == 15) {   // last block: all other atomics visible
            out[1048576] = g_loss * (1.0f + BETA) / 1048576.0f;
            out[1048577] = expf(-g_ent);
            out[1048578] = (float)g_cu;
        }
    }
}

// ---------------- launch ----------------
extern "C" void kernel_launch(void* const* d_in, const int* in_sizes, int n_in,
                              void* d_out, int out_size) {
    const float* z   = (const float*)d_in[0];   // (16,64,32,32)
    const float* emb = (const float*)d_in[1];   // (16384,64)
    float* out = (float*)d_out;

    cudaFuncSetAttribute(k_split, cudaFuncAttributeMaxDynamicSharedMemorySize, TILE2_BYTES);
    cudaFuncSetAttribute(k_mma,   cudaFuncAttributeMaxDynamicSharedMemorySize, SM_TOT);

    k_split<<<256, 256, TILE2_BYTES>>>(z, emb);
    k_mma<<<128 * NCH, 256, SM_TOT>>>(out);
    k_merge<<<16, 1024>>>(out);
    k_zq<<<1024, 256>>>(z, emb, out);
    k_ent<<<16, 1024>>>(out);
}

// round 10
// speedup vs baseline: 1.0238x; 1.0238x over previous
#include <cuda_runtime.h>
#include <cuda_fp16.h>
#include <math.h>
#include <stdint.h>

#define NT 16384
#define NE 16384
#define BETA 0.25f

#define RS2 136                     // halves per padded row (128 data + 8 pad)
#define RB2 272                     // bytes per row (17*16 -> conflict-free ldmatrix)
#define TILE2_BYTES (128 * RB2)     // 34816
#define CHUNK2 (TILE2_BYTES / 16)   // 2176

// ---------------- static device scratch ----------------
__device__ __half g_zf[16384 * RS2];  // A = [h_z | l_z], padded rows
__device__ __half g_ef[16384 * RS2];  // B = [h_E | l_E], E = 4096*e
__device__ float g_enorm[NE];
__device__ float g_znorm[NT];
__device__ int   g_idx[NT];
__device__ int   g_counts[NE];
__device__ float g_loss;
__device__ float g_ent;
__device__ int   g_cu;
__device__ int   g_tick;

// ---------------- helpers ----------------
__device__ __forceinline__ uint32_t smem_u32(const void* p) {
    uint32_t a;
    asm("{ .reg .u64 t; cvta.to.shared.u64 t, %1; cvt.u32.u64 %0, t; }" : "=r"(a) : "l"(p));
    return a;
}
__device__ __forceinline__ void split2h(float v, __half& h, __half& l) {
    __half hh = __float2half_rn(v);
    float r = __fsub_rn(v, __half2float(hh));   // exact
    h = hh; l = __float2half_rn(r);
}

#define CP_ASYNC16(dst_u32, src_ptr) \
    asm volatile("cp.async.cg.shared.global [%0], [%1], 16;\n" :: "r"(dst_u32), "l"(src_ptr))
#define CP_COMMIT()  asm volatile("cp.async.commit_group;\n" ::: "memory")
#define CP_WAIT0()   asm volatile("cp.async.wait_group 0;\n" ::: "memory")

#define LDSM_X4(r, addr) \
    asm volatile("ldmatrix.sync.aligned.m8n8.x4.shared.b16 {%0,%1,%2,%3}, [%4];" \
        : "=r"((r)[0]), "=r"((r)[1]), "=r"((r)[2]), "=r"((r)[3]) : "r"(addr))
#define LDSM_X2(r, addr) \
    asm volatile("ldmatrix.sync.aligned.m8n8.x2.shared.b16 {%0,%1}, [%2];" \
        : "=r"((r)[0]), "=r"((r)[1]) : "r"(addr))

__device__ __forceinline__ void mma16816(float* c, const uint32_t* a, const uint32_t* b) {
    asm volatile(
        "mma.sync.aligned.m16n8k16.row.col.f32.f16.f16.f32 "
        "{%0,%1,%2,%3}, {%4,%5,%6,%7}, {%8,%9}, {%0,%1,%2,%3};"
        : "+f"(c[0]), "+f"(c[1]), "+f"(c[2]), "+f"(c[3])
        : "r"(a[0]), "r"(a[1]), "r"(a[2]), "r"(a[3]), "r"(b[0]), "r"(b[1]));
}

// ---------------- prep (fused): split z and E=4096*e; norms; zero state ----------------
__global__ void k_split(const float* __restrict__ z, const float* __restrict__ emb) {
    extern __shared__ __half st[];          // 128 * RS2 halves = 34816 B
    int blk = blockIdx.x;                   // 0..127 z tiles, 128..255 e subtiles
    int tid = threadIdx.x;                  // 256
    if (blk < 128) {
        int tile = blk;
        int b = tile >> 3, hw0 = (tile & 7) << 7;
        for (int idx = tid; idx < 8192; idx += 256) {
            int k = idx >> 7, tl = idx & 127;
            float v = z[((size_t)(b * 64 + k) << 10) + hw0 + tl];
            __half h, l; split2h(v, h, l);
            st[tl * RS2 + k]      = h;
            st[tl * RS2 + 64 + k] = l;
        }
        __syncthreads();
        float4* dst = (float4*)(g_zf + (size_t)tile * 128 * RS2);
        const float4* src = (const float4*)st;
        for (int i = tid; i < CHUNK2; i += 256) dst[i] = src[i];
        if (tid < 128) {
            float s = 0.f;
            for (int k = 0; k < 64; k++) {
                float v = z[((size_t)(b * 64 + k) << 10) + hw0 + tid];
                s += v * v;
            }
            g_znorm[(tile << 7) + tid] = s;
        }
        if (tile == 0 && tid == 0) { g_loss = 0.f; g_ent = 0.f; g_cu = 0; g_tick = 0; }
    } else {
        int sub = blk - 128;
        int n0 = sub << 7;
        for (int idx = tid; idx < 8192; idx += 256) {
            int nl = idx >> 6, k = idx & 63;
            float v = emb[(size_t)(n0 + nl) * 64 + k] * 4096.0f;   // exact scale
            __half h, l; split2h(v, h, l);
            st[nl * RS2 + k]      = h;
            st[nl * RS2 + 64 + k] = l;
        }
        __syncthreads();
        float4* dst = (float4*)(g_ef + (size_t)sub * 128 * RS2);
        const float4* src = (const float4*)st;
        for (int i = tid; i < CHUNK2; i += 256) dst[i] = src[i];
        if (tid < 128) {
            float s = 0.f;
            for (int k = 0; k < 64; k++) {
                float v = emb[(size_t)(n0 + tid) * 64 + k];
                s += v * v;
            }
            g_enorm[n0 + tid] = s;
            g_counts[n0 + tid] = 0;
        }
    }
}

// ---------------- building blocks ----------------
__device__ __forceinline__ void load_en(int j, int nbw, int lane, float en[8]) {
#pragma unroll
    for (int ni = 0; ni < 4; ni++) {
        int c0 = nbw + ni * 8 + (lane & 3) * 2;
        en[ni * 2]     = __ldg(&g_enorm[(j << 7) + c0]);
        en[ni * 2 + 1] = __ldg(&g_enorm[(j << 7) + c0 + 1]);
    }
}

// full-subtile mma: A frags loaded ONCE per ks for all 4 ni (R6 structure)
__device__ __forceinline__ void mma_phase(uint32_t a_base, uint32_t b_base,
                                          float acc[4][4][4]) {
#pragma unroll
    for (int mi = 0; mi < 4; mi++)
#pragma unroll
        for (int ni = 0; ni < 4; ni++)
#pragma unroll
            for (int q = 0; q < 4; q++) acc[mi][ni][q] = 0.f;
#pragma unroll
    for (int ks = 0; ks < 4; ks++) {
        uint32_t ah[4][4], al[4][4], bh[4][2], bl[4][2];
#pragma unroll
        for (int mi = 0; mi < 4; mi++) {
            LDSM_X4(ah[mi], a_base + mi * 16 * RB2 + ks * 32);
            LDSM_X4(al[mi], a_base + mi * 16 * RB2 + 128 + ks * 32);
        }
#pragma unroll
        for (int ni = 0; ni < 4; ni++) {
            LDSM_X2(bh[ni], b_base + ni * 8 * RB2 + ks * 32);
            LDSM_X2(bl[ni], b_base + ni * 8 * RB2 + 128 + ks * 32);
        }
#pragma unroll
        for (int mi = 0; mi < 4; mi++)
#pragma unroll
            for (int ni = 0; ni < 4; ni++)
                mma16816(acc[mi][ni], ah[mi], bh[ni]);
#pragma unroll
        for (int mi = 0; mi < 4; mi++)
#pragma unroll
            for (int ni = 0; ni < 4; ni++)
                mma16816(acc[mi][ni], al[mi], bh[ni]);
#pragma unroll
        for (int mi = 0; mi < 4; mi++)
#pragma unroll
            for (int ni = 0; ni < 4; ni++)
                mma16816(acc[mi][ni], ah[mi], bl[ni]);
    }
}

// epilogue: d = fl(fl(zn+en) - acc*2^-11). FMNMX min-tree per row, rare index
// resolve (descending overwrite scan => lowest n among exact-equal values).
__device__ __forceinline__ void epi_tile(const float acc[4][4][4], const float en[8],
                                         const float zn[8], int j, int nbw, int lane,
                                         float bv[8], int bi[8]) {
#pragma unroll
    for (int mi = 0; mi < 4; mi++) {
#pragma unroll
        for (int rh = 0; rh < 2; rh++) {
            int r = mi * 2 + rh;
            float d[4][2];
#pragma unroll
            for (int ni = 0; ni < 4; ni++) {
#pragma unroll
                for (int col = 0; col < 2; col++) {
                    float c = __fadd_rn(zn[r], en[ni * 2 + col]);
                    d[ni][col] = fmaf(acc[mi][ni][rh * 2 + col], -0x1p-11f, c);
                }
            }
            float m = fminf(fminf(fminf(d[0][0], d[0][1]), fminf(d[1][0], d[1][1])),
                            fminf(fminf(d[2][0], d[2][1]), fminf(d[3][0], d[3][1])));
            if (m < bv[r]) {
                bv[r] = m;
                int nb = (j << 7) + nbw + (lane & 3) * 2;
                int sel = nb + 3 * 8 + 1;
#pragma unroll
                for (int ni = 3; ni >= 0; ni--)
#pragma unroll
                    for (int col = 1; col >= 0; col--)
                        if (d[ni][col] == m) sel = nb + ni * 8 + col;
                bi[r] = sel;
            }
        }
    }
}

// ---------------- main: fp16 mma.sync distance GEMM + fused argmin -------------------
// smem: A [0,34816) | B ring x4 [34816, 174080)
#define SM_TOT (5 * TILE2_BYTES)

__global__ void __launch_bounds__(256, 1) k_mma(float* __restrict__ out) {
    extern __shared__ __align__(16) unsigned char sm[];
    uint32_t sb = smem_u32(sm);
    const uint32_t SA = sb, SBB = sb + TILE2_BYTES;   // B ring base

    int tid = threadIdx.x, lane = tid & 31, wid = tid >> 5;
    int mw = wid & 1, nw = wid >> 1;        // 2 x 4 warp grid
    int mbase = mw * 64, nbw = nw * 32;     // warp tile 64 x 32

    // prolog: A tile + B subtiles 0 and 1 (ring slots 0, 1)
    {
        const char* gz = (const char*)(g_zf + (size_t)blockIdx.x * 128 * RS2);
        for (int i = tid; i < CHUNK2; i += 256) CP_ASYNC16(SA + i * 16, gz + i * 16);
        const char* ge0 = (const char*)g_ef;
        for (int i = tid; i < CHUNK2; i += 256) CP_ASYNC16(SBB + i * 16, ge0 + i * 16);
        const char* ge1 = (const char*)(g_ef + (size_t)128 * RS2);
        for (int i = tid; i < CHUNK2; i += 256)
            CP_ASYNC16(SBB + TILE2_BYTES + i * 16, ge1 + i * 16);
        CP_COMMIT(); CP_WAIT0();
    }
    __syncthreads();

    // per-thread rows: r = mbase + mi*16 + rh*8 + (lane>>2)
    float zn[8];
#pragma unroll
    for (int mi = 0; mi < 4; mi++)
#pragma unroll
        for (int rh = 0; rh < 2; rh++)
            zn[mi * 2 + rh] = g_znorm[(blockIdx.x << 7) + mbase + mi * 16 + rh * 8 + (lane >> 2)];

    float bv[8]; int bi[8];
#pragma unroll
    for (int r = 0; r < 8; r++) { bv[r] = 3.0e38f; bi[r] = 0; }

    // ldmatrix base addresses (conflict-free with 272B row stride)
    uint32_t a_base = SA + (uint32_t)(mbase + (lane & 15)) * RB2 + ((lane >> 4) & 1) * 16;
    uint32_t b_roff = (uint32_t)(nbw + (lane & 7)) * RB2 + ((lane >> 3) & 1) * 16;

    float acc[4][4][4];

    // pair loop: barrier every 2 subtiles; 4-slot B ring lets warps skew
    // within the pair so one warp's fp32 epilogue overlaps another's HMMA.
    for (int k = 0; k < 64; k++) {
        int j0 = 2 * k, j1 = 2 * k + 1;
        uint32_t base0 = SBB + (uint32_t)((k & 1) ? 2 : 0) * TILE2_BYTES;  // slot of j0
        uint32_t Bj0 = base0, Bj1 = base0 + TILE2_BYTES;
        uint32_t Bp0 = SBB + (uint32_t)((k & 1) ? 0 : 2) * TILE2_BYTES;    // slot of j0+2
        uint32_t Bp1 = Bp0 + TILE2_BYTES;

        if (j0 + 2 < 128) {   // prefetch next pair (overwrites slots consumed 2 iters ago)
            const char* s0 = (const char*)(g_ef + (size_t)(j0 + 2) * 128 * RS2);
            for (int i = tid; i < CHUNK2; i += 256) CP_ASYNC16(Bp0 + i * 16, s0 + i * 16);
            const char* s1 = (const char*)(g_ef + (size_t)(j1 + 2) * 128 * RS2);
            for (int i = tid; i < CHUNK2; i += 256) CP_ASYNC16(Bp1 + i * 16, s1 + i * 16);
            CP_COMMIT();
        }

        float en[8];
        load_en(j0, nbw, lane, en);
        mma_phase(a_base, Bj0 + b_roff, acc);
        epi_tile(acc, en, zn, j0, nbw, lane, bv, bi);

        load_en(j1, nbw, lane, en);
        mma_phase(a_base, Bj1 + b_roff, acc);
        epi_tile(acc, en, zn, j1, nbw, lane, bv, bi);

        CP_WAIT0();
        __syncthreads();
    }

    // quad reduce (cols within warp): lanes differing in (lane&3)
#pragma unroll
    for (int r = 0; r < 8; r++) {
#pragma unroll
        for (int off = 1; off <= 2; off <<= 1) {
            float ov = __shfl_xor_sync(0xffffffffu, bv[r], off);
            int   oi = __shfl_xor_sync(0xffffffffu, bi[r], off);
            if (ov < bv[r] || (ov == bv[r] && oi < bi[r])) { bv[r] = ov; bi[r] = oi; }
        }
    }
    __syncthreads();
    float* rv = (float*)(sm + TILE2_BYTES);          // reuse B ring: 128 rows x 4 nwarps
    int*   ri = (int*)(sm + TILE2_BYTES + 2048);
    if ((lane & 3) == 0) {
#pragma unroll
        for (int r = 0; r < 8; r++) {
            int row = mbase + (r >> 1) * 16 + (r & 1) * 8 + (lane >> 2);
            rv[row * 4 + nw] = bv[r];
            ri[row * 4 + nw] = bi[r];
        }
    }
    __syncthreads();
    if (tid < 128) {
        float v = rv[tid * 4]; int ii = ri[tid * 4];
#pragma unroll
        for (int x = 1; x < 4; x++) {
            float ov = rv[tid * 4 + x]; int oi = ri[tid * 4 + x];
            if (ov < v || (ov == v && oi < ii)) { v = ov; ii = oi; }
        }
        int t = (blockIdx.x << 7) + tid;
        g_idx[t] = ii;
        out[1048579 + t] = (float)ii;
        atomicAdd(&g_counts[ii], 1);
    }
}

// ---------------- z_q gather + loss accumulation ----------------
__global__ void k_zq(const float* __restrict__ z, const float* __restrict__ emb,
                     float* __restrict__ out) {
    int p = blockIdx.x;            // 1024 planes = (b,c)
    int b = p >> 6, c = p & 63;
    int tid = threadIdx.x;         // 256
    float ls = 0.f;
    for (int hw = tid; hw < 1024; hw += 256) {
        int t = (b << 10) + hw;
        int id = g_idx[t];
        float v  = emb[(size_t)id * 64 + c];
        float zv = z[(size_t)p * 1024 + hw];
        out[(size_t)p * 1024 + hw] = v;
        float df = v - zv;
        ls += df * df;
    }
    __shared__ float red[8];
    for (int o = 16; o > 0; o >>= 1) ls += __shfl_down_sync(0xffffffff, ls, o);
    if ((tid & 31) == 0) red[tid >> 5] = ls;
    __syncthreads();
    if (tid == 0) {
        float s = 0.f;
        for (int w = 0; w < 8; w++) s += red[w];
        atomicAdd(&g_loss, s);
    }
}

// ---------------- entropy (parallel) + final scalar writes (ticket) ----------------
__global__ void k_ent(float* __restrict__ out) {
    int tid = threadIdx.x;                      // 1024, grid 16
    int n = blockIdx.x * 1024 + tid;
    int c = g_counts[n];
    float avg = (float)c * (1.0f / 16384.0f);
    float term = avg * logf(avg + 1e-10f);
    int cu = (c > 0) ? 1 : 0;
    for (int o = 16; o > 0; o >>= 1) {
        term += __shfl_down_sync(0xffffffffu, term, o);
        cu   += __shfl_down_sync(0xffffffffu, cu, o);
    }
    __shared__ float se[32]; __shared__ int sc[32];
    if ((tid & 31) == 0) { se[tid >> 5] = term; sc[tid >> 5] = cu; }
    __syncthreads();
    if (tid == 0) {
        float s = 0.f; int k = 0;
        for (int w = 0; w < 32; w++) { s += se[w]; k += sc[w]; }
        atomicAdd(&g_ent, s);
        atomicAdd(&g_cu, k);
        __threadfence();
        int tk = atomicAdd(&g_tick, 1);
        if (tk == 15) {   // last block: all other atomics visible
            out[1048576] = g_loss * (1.0f + BETA) / 1048576.0f;
            out[1048577] = expf(-g_ent);
            out[1048578] = (float)g_cu;
        }
    }
}

// ---------------- launch ----------------
extern "C" void kernel_launch(void* const* d_in, const int* in_sizes, int n_in,
                              void* d_out, int out_size) {
    const float* z   = (const float*)d_in[0];   // (16,64,32,32)
    const float* emb = (const float*)d_in[1];   // (16384,64)
    float* out = (float*)d_out;

    cudaFuncSetAttribute(k_split, cudaFuncAttributeMaxDynamicSharedMemorySize, TILE2_BYTES);
    cudaFuncSetAttribute(k_mma,   cudaFuncAttributeMaxDynamicSharedMemorySize, SM_TOT);

    k_split<<<256, 256, TILE2_BYTES>>>(z, emb);
    k_mma<<<128, 256, SM_TOT>>>(out);
    k_zq<<<1024, 256>>>(z, emb, out);
    k_ent<<<16, 1024>>>(out);
}